// round 13
// baseline (speedup 1.0000x reference)
#include <cuda_runtime.h>
#include <cuda_bf16.h>
#include <cstdint>

// word2vec negative-sampling loss:
//   second_emb  [200000, 128] f32   (low reuse   -> L2 evict_first)
//   context_emb [200000, 128] f32   (~3.9x reuse -> L2 evict_last)
//   v_i, v_j    [131072] i32
//   negsamples  [5, 131072] i32
// out: scalar f32 = -mean_b( logsig(vi.vj) + sum_k logsig(-vi.neg_k) )
//
// Structure (FINAL after 5 failed alternatives): plain two-kernel split.
//  - gpu fence = CCTL.IVALL L1 flush (R2/R3 regression)
//  - release atomic protocol (R6 regression)
//  - relaxed packed atomicAdd, 1/block (R9: +35us, LTS atomic serialization)
//  - PDL pre-scheduled reduce (R10: +18us, co-residency interference)
//  - forced reg cap (R11: spills, +0.7us)
// Occupancy ladder (measured): 48 warps/SM -> 51.7us, 56 -> 49.7us.
// This round: TPB=128 -> 60 warps/SM (93.75%), the natural max at 34 regs.

#define EMBED 128
#define NUM_NEG 5
#define TPB 128
#define WPB 4                       // warps per block
#define NPART 32768                 // batch / WPB for batch=131072

__device__ float g_partials[NPART];

__device__ __forceinline__ float fast_log_sigmoid(float x) {
    // logsig(x) = min(x,0) - log(1 + exp(-|x|))
    return fminf(x, 0.0f) - __logf(1.0f + __expf(-fabsf(x)));
}

__device__ __forceinline__ float dot4(float4 a, float4 b) {
    return fmaf(a.x, b.x, fmaf(a.y, b.y, fmaf(a.z, b.z, a.w * b.w)));
}

__device__ __forceinline__ uint64_t mk_policy_evict_first() {
    uint64_t p;
    asm("createpolicy.fractional.L2::evict_first.b64 %0, 1.0;" : "=l"(p));
    return p;
}

__device__ __forceinline__ uint64_t mk_policy_evict_last() {
    uint64_t p;
    asm("createpolicy.fractional.L2::evict_last.b64 %0, 1.0;" : "=l"(p));
    return p;
}

__device__ __forceinline__ float4 ldg_hint(const float4* p, uint64_t policy) {
    float4 v;
    asm volatile("ld.global.nc.L2::cache_hint.v4.f32 {%0,%1,%2,%3}, [%4], %5;"
                 : "=f"(v.x), "=f"(v.y), "=f"(v.z), "=f"(v.w)
                 : "l"(p), "l"(policy));
    return v;
}

__global__ void __launch_bounds__(TPB)
w2v_main(const float* __restrict__ second_emb,
         const float* __restrict__ context_emb,
         const int* __restrict__ v_i,
         const int* __restrict__ v_j,
         const int* __restrict__ negs,
         int batch)
{
    const int lane = threadIdx.x & 31;
    const int wid  = threadIdx.x >> 5;
    const int e    = blockIdx.x * WPB + wid;    // one element per warp
                                                // (grid exactly tiles batch)

    const uint64_t pol_stream   = mk_policy_evict_first();
    const uint64_t pol_resident = mk_policy_evict_last();

    // ---- lane-distributed index gather: ONE LDG for all 7 indices ----
    int myidx = 0;
    if (lane < 7) {
        const int* p;
        if (lane == 0)      p = v_i + e;
        else if (lane == 1) p = v_j + e;
        else                p = negs + (lane - 2) * batch + e;
        myidx = __ldg(p);
    }
    const int ivi = __shfl_sync(0xFFFFFFFFu, myidx, 0);
    const int ivj = __shfl_sync(0xFFFFFFFFu, myidx, 1);
    int ineg[NUM_NEG];
    #pragma unroll
    for (int k = 0; k < NUM_NEG; k++)
        ineg[k] = __shfl_sync(0xFFFFFFFFu, myidx, k + 2);

    // 32-bit row offsets (200000*128 < 2^31)
    const float4* vi_row = reinterpret_cast<const float4*>(
        second_emb + (unsigned)ivi * EMBED);
    float4 a = ldg_hint(&vi_row[lane], pol_stream);

    // all 6 context rows issued before consumption (MLP)
    float4 r[NUM_NEG + 1];
    const float4* vj_row = reinterpret_cast<const float4*>(
        context_emb + (unsigned)ivj * EMBED);
    r[0] = ldg_hint(&vj_row[lane], pol_resident);
    #pragma unroll
    for (int k = 0; k < NUM_NEG; k++) {
        const float4* nrow = reinterpret_cast<const float4*>(
            context_emb + (unsigned)ineg[k] * EMBED);
        r[k + 1] = ldg_hint(&nrow[lane], pol_resident);
    }

    float d[NUM_NEG + 1];
    #pragma unroll
    for (int j = 0; j < NUM_NEG + 1; j++)
        d[j] = dot4(a, r[j]);

    // split-butterfly: fold halves once, then each half-warp finishes
    // 3 of the 6 dot reductions (21 shuffles instead of 30)
    #pragma unroll
    for (int j = 0; j < 6; j++)
        d[j] += __shfl_xor_sync(0xFFFFFFFFu, d[j], 16);

    const bool hi = lane >= 16;
    float v0 = hi ? d[3] : d[0];
    float v1 = hi ? d[4] : d[1];
    float v2 = hi ? d[5] : d[2];

    #pragma unroll
    for (int off = 8; off > 0; off >>= 1) {
        v0 += __shfl_xor_sync(0xFFFFFFFFu, v0, off);
        v1 += __shfl_xor_sync(0xFFFFFFFFu, v1, off);
        v2 += __shfl_xor_sync(0xFFFFFFFFu, v2, off);
    }
    // low half lanes hold D0,D1,D2; high half D3,D4,D5 (replicated)

    // distributed logsig: lanes {0,1,2,16,17,18} each own one term
    const int sl = lane & 15;
    float x = v0;
    x = (sl == 1) ? v1 : x;
    x = (sl == 2) ? v2 : x;
    float arg = (lane == 0) ? x : -x;      // positive term only for D0
    float t = fast_log_sigmoid(arg);
    t = (sl < 3) ? t : 0.0f;

    t += __shfl_xor_sync(0xFFFFFFFFu, t, 16);
    t += __shfl_xor_sync(0xFFFFFFFFu, t, 1);
    t += __shfl_xor_sync(0xFFFFFFFFu, t, 2);
    const float elem_loss = t;             // lane 0 holds element loss

    // block reduce (deterministic): 4 warp values -> 1 partial
    __shared__ float ws[WPB];
    if (lane == 0)
        ws[wid] = elem_loss;
    __syncthreads();

    if (threadIdx.x < 32) {
        float s = (threadIdx.x < WPB) ? ws[threadIdx.x] : 0.0f;
        #pragma unroll
        for (int off = 2; off > 0; off >>= 1)
            s += __shfl_xor_sync(0xFFFFFFFFu, s, off);
        if (threadIdx.x == 0)
            g_partials[blockIdx.x] = s;
    }
}

__global__ void __launch_bounds__(1024)
w2v_reduce(float* __restrict__ out, float inv_batch)
{
    // 32768 partials = 8192 float4; 1024 threads x 8 independent float4
    const float4* p = reinterpret_cast<const float4*>(g_partials);
    const int tid = threadIdx.x;

    float4 s4 = make_float4(0.f, 0.f, 0.f, 0.f);
    #pragma unroll
    for (int i = 0; i < 8; i++) {
        float4 v = __ldg(&p[tid + i * 1024]);
        s4.x += v.x; s4.y += v.y; s4.z += v.z; s4.w += v.w;
    }
    float s = (s4.x + s4.y) + (s4.z + s4.w);

    #pragma unroll
    for (int off = 16; off > 0; off >>= 1)
        s += __shfl_xor_sync(0xFFFFFFFFu, s, off);

    __shared__ float sh[32];
    if ((tid & 31) == 0)
        sh[tid >> 5] = s;
    __syncthreads();

    if (tid < 32) {
        float t = sh[tid];
        #pragma unroll
        for (int off = 16; off > 0; off >>= 1)
            t += __shfl_xor_sync(0xFFFFFFFFu, t, off);
        if (tid == 0)
            out[0] = -t * inv_batch;
    }
}

extern "C" void kernel_launch(void* const* d_in, const int* in_sizes, int n_in,
                              void* d_out, int out_size)
{
    const float* second_emb  = (const float*)d_in[0];
    const float* context_emb = (const float*)d_in[1];
    const int*   v_i         = (const int*)d_in[2];
    const int*   v_j         = (const int*)d_in[3];
    const int*   negs        = (const int*)d_in[4];

    const int batch  = in_sizes[2];                 // 131072
    const int blocks = (batch + WPB - 1) / WPB;     // 32768

    w2v_main<<<blocks, TPB>>>(second_emb, context_emb, v_i, v_j, negs, batch);
    w2v_reduce<<<1, 1024>>>((float*)d_out, 1.0f / (float)batch);
}

// round 14
// speedup vs baseline: 1.0576x; 1.0576x over previous
#include <cuda_runtime.h>
#include <cuda_bf16.h>
#include <cstdint>

// word2vec negative-sampling loss:
//   second_emb  [200000, 128] f32   (low reuse   -> L2 evict_first)
//   context_emb [200000, 128] f32   (~3.9x reuse -> L2 evict_last)
//   v_i, v_j    [131072] i32
//   negsamples  [5, 131072] i32
// out: scalar f32 = -mean_b( logsig(vi.vj) + sum_k logsig(-vi.neg_k) )
//
// Structure (FINAL): plain two-kernel split; all fusion/PDL/atomic variants
// measured as regressions (R2,R3,R6,R9,R10). Occupancy ladder measured:
// 48 warps/SM 51.7us, 56 -> 49.7, 60 -> main 44.5 (TPB=128).
// This round: TPB=128 (60 warps/SM) + 2 elements per warp -> 16384 partials
// (reduce back to its 4.2us shape) + paired index load (1 LDG for both).

#define EMBED 128
#define NUM_NEG 5
#define TPB 128
#define WPB 4                       // warps per block
#define EPW 2                       // elements per warp
#define NPART 16384                 // batch / (WPB*EPW)

__device__ float g_partials[NPART];

__device__ __forceinline__ float fast_log_sigmoid(float x) {
    return fminf(x, 0.0f) - __logf(1.0f + __expf(-fabsf(x)));
}

__device__ __forceinline__ float dot4(float4 a, float4 b) {
    return fmaf(a.x, b.x, fmaf(a.y, b.y, fmaf(a.z, b.z, a.w * b.w)));
}

__device__ __forceinline__ uint64_t mk_policy_evict_first() {
    uint64_t p;
    asm("createpolicy.fractional.L2::evict_first.b64 %0, 1.0;" : "=l"(p));
    return p;
}

__device__ __forceinline__ uint64_t mk_policy_evict_last() {
    uint64_t p;
    asm("createpolicy.fractional.L2::evict_last.b64 %0, 1.0;" : "=l"(p));
    return p;
}

__device__ __forceinline__ float4 ldg_hint(const float4* p, uint64_t policy) {
    float4 v;
    asm volatile("ld.global.nc.L2::cache_hint.v4.f32 {%0,%1,%2,%3}, [%4], %5;"
                 : "=f"(v.x), "=f"(v.y), "=f"(v.z), "=f"(v.w)
                 : "l"(p), "l"(policy));
    return v;
}

// one element: 7 row gathers -> 6 dots -> warp-reduced -> loss (lane 0)
__device__ __forceinline__ float elem_loss_warp(
    const float* __restrict__ second_emb,
    const float* __restrict__ context_emb,
    int ivi, int ivj, const int* ineg,
    int lane, uint64_t pol_stream, uint64_t pol_resident)
{
    const float4* vi_row = reinterpret_cast<const float4*>(
        second_emb + (unsigned)ivi * EMBED);
    float4 a = ldg_hint(&vi_row[lane], pol_stream);

    float4 r[NUM_NEG + 1];
    const float4* vj_row = reinterpret_cast<const float4*>(
        context_emb + (unsigned)ivj * EMBED);
    r[0] = ldg_hint(&vj_row[lane], pol_resident);
    #pragma unroll
    for (int k = 0; k < NUM_NEG; k++) {
        const float4* nrow = reinterpret_cast<const float4*>(
            context_emb + (unsigned)ineg[k] * EMBED);
        r[k + 1] = ldg_hint(&nrow[lane], pol_resident);
    }

    float d[NUM_NEG + 1];
    #pragma unroll
    for (int j = 0; j < NUM_NEG + 1; j++)
        d[j] = dot4(a, r[j]);

    // split-butterfly: 21 shuffles instead of 30
    #pragma unroll
    for (int j = 0; j < 6; j++)
        d[j] += __shfl_xor_sync(0xFFFFFFFFu, d[j], 16);

    const bool hi = lane >= 16;
    float v0 = hi ? d[3] : d[0];
    float v1 = hi ? d[4] : d[1];
    float v2 = hi ? d[5] : d[2];

    #pragma unroll
    for (int off = 8; off > 0; off >>= 1) {
        v0 += __shfl_xor_sync(0xFFFFFFFFu, v0, off);
        v1 += __shfl_xor_sync(0xFFFFFFFFu, v1, off);
        v2 += __shfl_xor_sync(0xFFFFFFFFu, v2, off);
    }

    // distributed logsig: lanes {0,1,2,16,17,18} each own one term
    const int sl = lane & 15;
    float x = v0;
    x = (sl == 1) ? v1 : x;
    x = (sl == 2) ? v2 : x;
    float arg = (lane == 0) ? x : -x;
    float t = fast_log_sigmoid(arg);
    t = (sl < 3) ? t : 0.0f;

    t += __shfl_xor_sync(0xFFFFFFFFu, t, 16);
    t += __shfl_xor_sync(0xFFFFFFFFu, t, 1);
    t += __shfl_xor_sync(0xFFFFFFFFu, t, 2);
    return t;   // lane 0 holds full element loss
}

__global__ void __launch_bounds__(TPB)
w2v_main(const float* __restrict__ second_emb,
         const float* __restrict__ context_emb,
         const int* __restrict__ v_i,
         const int* __restrict__ v_j,
         const int* __restrict__ negs,
         int batch)
{
    const int lane = threadIdx.x & 31;
    const int wid  = threadIdx.x >> 5;
    const int g    = blockIdx.x * WPB + wid;    // warp's group id
    const int e0   = g * EPW;                   // two adjacent elements
    const int e1   = e0 + 1;                    // (grid exactly tiles batch)

    const uint64_t pol_stream   = mk_policy_evict_first();
    const uint64_t pol_resident = mk_policy_evict_last();

    // ---- paired index gather: ONE LDG for all 14 indices ----
    // lanes 0-6: e0's {v_i, v_j, neg0..neg4}; lanes 16-22: e1's
    int myidx = 0;
    {
        const int sl = lane & 15;
        const int ee = (lane < 16) ? e0 : e1;
        if (sl < 7) {
            const int* p;
            if (sl == 0)      p = v_i + ee;
            else if (sl == 1) p = v_j + ee;
            else              p = negs + (sl - 2) * batch + ee;
            myidx = __ldg(p);
        }
    }
    const int ivi0 = __shfl_sync(0xFFFFFFFFu, myidx, 0);
    const int ivj0 = __shfl_sync(0xFFFFFFFFu, myidx, 1);
    const int ivi1 = __shfl_sync(0xFFFFFFFFu, myidx, 16);
    const int ivj1 = __shfl_sync(0xFFFFFFFFu, myidx, 17);
    int ineg0[NUM_NEG], ineg1[NUM_NEG];
    #pragma unroll
    for (int k = 0; k < NUM_NEG; k++) {
        ineg0[k] = __shfl_sync(0xFFFFFFFFu, myidx, k + 2);
        ineg1[k] = __shfl_sync(0xFFFFFFFFu, myidx, k + 18);
    }

    float loss = elem_loss_warp(second_emb, context_emb, ivi0, ivj0, ineg0,
                                lane, pol_stream, pol_resident);
    loss      += elem_loss_warp(second_emb, context_emb, ivi1, ivj1, ineg1,
                                lane, pol_stream, pol_resident);

    // block reduce (deterministic): 4 warp values -> 1 partial
    __shared__ float ws[WPB];
    if (lane == 0)
        ws[wid] = loss;
    __syncthreads();

    if (threadIdx.x < 32) {
        float s = (threadIdx.x < WPB) ? ws[threadIdx.x] : 0.0f;
        #pragma unroll
        for (int off = 2; off > 0; off >>= 1)
            s += __shfl_xor_sync(0xFFFFFFFFu, s, off);
        if (threadIdx.x == 0)
            g_partials[blockIdx.x] = s;
    }
}

__global__ void __launch_bounds__(1024)
w2v_reduce(float* __restrict__ out, float inv_batch)
{
    // 16384 partials = 4096 float4; 1024 threads x 4 independent float4
    const float4* p = reinterpret_cast<const float4*>(g_partials);
    const int tid = threadIdx.x;

    float4 s4 = make_float4(0.f, 0.f, 0.f, 0.f);
    #pragma unroll
    for (int i = 0; i < 4; i++) {
        float4 v = __ldg(&p[tid + i * 1024]);
        s4.x += v.x; s4.y += v.y; s4.z += v.z; s4.w += v.w;
    }
    float s = (s4.x + s4.y) + (s4.z + s4.w);

    #pragma unroll
    for (int off = 16; off > 0; off >>= 1)
        s += __shfl_xor_sync(0xFFFFFFFFu, s, off);

    __shared__ float sh[32];
    if ((tid & 31) == 0)
        sh[tid >> 5] = s;
    __syncthreads();

    if (tid < 32) {
        float t = sh[tid];
        #pragma unroll
        for (int off = 16; off > 0; off >>= 1)
            t += __shfl_xor_sync(0xFFFFFFFFu, t, off);
        if (tid == 0)
            out[0] = -t * inv_batch;
    }
}

extern "C" void kernel_launch(void* const* d_in, const int* in_sizes, int n_in,
                              void* d_out, int out_size)
{
    const float* second_emb  = (const float*)d_in[0];
    const float* context_emb = (const float*)d_in[1];
    const int*   v_i         = (const int*)d_in[2];
    const int*   v_j         = (const int*)d_in[3];
    const int*   negs        = (const int*)d_in[4];

    const int batch  = in_sizes[2];                       // 131072
    const int blocks = (batch + WPB * EPW - 1) / (WPB * EPW);  // 16384

    w2v_main<<<blocks, TPB>>>(second_emb, context_emb, v_i, v_j, negs, batch);
    w2v_reduce<<<1, 1024>>>((float*)d_out, 1.0f / (float)batch);
}

// round 15
// speedup vs baseline: 1.1264x; 1.0650x over previous
#include <cuda_runtime.h>
#include <cuda_bf16.h>
#include <cstdint>

// word2vec negative-sampling loss:
//   second_emb  [200000, 128] f32   (low reuse   -> L2 evict_first)
//   context_emb [200000, 128] f32   (~3.9x reuse -> L2 evict_last)
//   v_i, v_j    [131072] i32
//   negsamples  [5, 131072] i32
// out: scalar f32 = -mean_b( logsig(vi.vj) + sum_k logsig(-vi.neg_k) )
//
// Structure (FINAL): plain two-kernel split; all fusion/PDL/atomic variants
// regressed (R2,R3,R6,R9,R10). Occupancy/ILP ladder measured:
//   48w EPW1: 51.7 | 56w EPW1: 49.7 | 60w EPW1: 49.9 | 60w EPW2: 47.2
// This round: EPW=4 -> 28 indices in ONE LDG, 4 independent element
// pipelines per warp (more loads in flight), partials 8192.

#define EMBED 128
#define NUM_NEG 5
#define TPB 128
#define WPB 4                       // warps per block
#define EPW 4                       // elements per warp
#define NPART 8192                  // batch / (WPB*EPW)

__device__ float g_partials[NPART];

__device__ __forceinline__ float fast_log_sigmoid(float x) {
    return fminf(x, 0.0f) - __logf(1.0f + __expf(-fabsf(x)));
}

__device__ __forceinline__ float dot4(float4 a, float4 b) {
    return fmaf(a.x, b.x, fmaf(a.y, b.y, fmaf(a.z, b.z, a.w * b.w)));
}

__device__ __forceinline__ uint64_t mk_policy_evict_first() {
    uint64_t p;
    asm("createpolicy.fractional.L2::evict_first.b64 %0, 1.0;" : "=l"(p));
    return p;
}

__device__ __forceinline__ uint64_t mk_policy_evict_last() {
    uint64_t p;
    asm("createpolicy.fractional.L2::evict_last.b64 %0, 1.0;" : "=l"(p));
    return p;
}

__device__ __forceinline__ float4 ldg_hint(const float4* p, uint64_t policy) {
    float4 v;
    asm volatile("ld.global.nc.L2::cache_hint.v4.f32 {%0,%1,%2,%3}, [%4], %5;"
                 : "=f"(v.x), "=f"(v.y), "=f"(v.z), "=f"(v.w)
                 : "l"(p), "l"(policy));
    return v;
}

// one element: 7 row gathers -> 6 dots -> warp-reduced -> loss (lane 0)
__device__ __forceinline__ float elem_loss_warp(
    const float* __restrict__ second_emb,
    const float* __restrict__ context_emb,
    int ivi, int ivj, const int* ineg,
    int lane, uint64_t pol_stream, uint64_t pol_resident)
{
    const float4* vi_row = reinterpret_cast<const float4*>(
        second_emb + (unsigned)ivi * EMBED);
    float4 a = ldg_hint(&vi_row[lane], pol_stream);

    float4 r[NUM_NEG + 1];
    const float4* vj_row = reinterpret_cast<const float4*>(
        context_emb + (unsigned)ivj * EMBED);
    r[0] = ldg_hint(&vj_row[lane], pol_resident);
    #pragma unroll
    for (int k = 0; k < NUM_NEG; k++) {
        const float4* nrow = reinterpret_cast<const float4*>(
            context_emb + (unsigned)ineg[k] * EMBED);
        r[k + 1] = ldg_hint(&nrow[lane], pol_resident);
    }

    float d[NUM_NEG + 1];
    #pragma unroll
    for (int j = 0; j < NUM_NEG + 1; j++)
        d[j] = dot4(a, r[j]);

    // split-butterfly: 21 shuffles instead of 30
    #pragma unroll
    for (int j = 0; j < 6; j++)
        d[j] += __shfl_xor_sync(0xFFFFFFFFu, d[j], 16);

    const bool hi = lane >= 16;
    float v0 = hi ? d[3] : d[0];
    float v1 = hi ? d[4] : d[1];
    float v2 = hi ? d[5] : d[2];

    #pragma unroll
    for (int off = 8; off > 0; off >>= 1) {
        v0 += __shfl_xor_sync(0xFFFFFFFFu, v0, off);
        v1 += __shfl_xor_sync(0xFFFFFFFFu, v1, off);
        v2 += __shfl_xor_sync(0xFFFFFFFFu, v2, off);
    }

    // distributed logsig: lanes {0,1,2,16,17,18} each own one term
    const int sl = lane & 15;
    float x = v0;
    x = (sl == 1) ? v1 : x;
    x = (sl == 2) ? v2 : x;
    float arg = (lane == 0) ? x : -x;
    float t = fast_log_sigmoid(arg);
    t = (sl < 3) ? t : 0.0f;

    t += __shfl_xor_sync(0xFFFFFFFFu, t, 16);
    t += __shfl_xor_sync(0xFFFFFFFFu, t, 1);
    t += __shfl_xor_sync(0xFFFFFFFFu, t, 2);
    return t;   // lane 0 holds full element loss
}

__global__ void __launch_bounds__(TPB)
w2v_main(const float* __restrict__ second_emb,
         const float* __restrict__ context_emb,
         const int* __restrict__ v_i,
         const int* __restrict__ v_j,
         const int* __restrict__ negs,
         int batch)
{
    const int lane = threadIdx.x & 31;
    const int wid  = threadIdx.x >> 5;
    const int g    = blockIdx.x * WPB + wid;    // warp's group id
    const int e0   = g * EPW;                   // 4 adjacent elements
                                                // (grid exactly tiles batch)

    const uint64_t pol_stream   = mk_policy_evict_first();
    const uint64_t pol_resident = mk_policy_evict_last();

    // ---- quad index gather: ONE LDG for all 28 indices ----
    // lane group q = lane>>3 handles element e0+q; sl = lane&7 in 0..6
    int myidx = 0;
    {
        const int sl = lane & 7;
        const int ee = e0 + (lane >> 3);
        if (sl < 7) {
            const int* p;
            if (sl == 0)      p = v_i + ee;
            else if (sl == 1) p = v_j + ee;
            else              p = negs + (sl - 2) * batch + ee;
            myidx = __ldg(p);
        }
    }

    int ivi[EPW], ivj[EPW], ineg[EPW][NUM_NEG];
    #pragma unroll
    for (int q = 0; q < EPW; q++) {
        ivi[q] = __shfl_sync(0xFFFFFFFFu, myidx, q * 8 + 0);
        ivj[q] = __shfl_sync(0xFFFFFFFFu, myidx, q * 8 + 1);
        #pragma unroll
        for (int k = 0; k < NUM_NEG; k++)
            ineg[q][k] = __shfl_sync(0xFFFFFFFFu, myidx, q * 8 + 2 + k);
    }

    float loss = 0.0f;
    #pragma unroll
    for (int q = 0; q < EPW; q++)
        loss += elem_loss_warp(second_emb, context_emb, ivi[q], ivj[q],
                               ineg[q], lane, pol_stream, pol_resident);

    // block reduce (deterministic): 4 warp values -> 1 partial
    __shared__ float ws[WPB];
    if (lane == 0)
        ws[wid] = loss;
    __syncthreads();

    if (threadIdx.x < 32) {
        float s = (threadIdx.x < WPB) ? ws[threadIdx.x] : 0.0f;
        #pragma unroll
        for (int off = 2; off > 0; off >>= 1)
            s += __shfl_xor_sync(0xFFFFFFFFu, s, off);
        if (threadIdx.x == 0)
            g_partials[blockIdx.x] = s;
    }
}

__global__ void __launch_bounds__(1024)
w2v_reduce(float* __restrict__ out, float inv_batch)
{
    // 8192 partials = 2048 float4; 1024 threads x 2 independent float4
    const float4* p = reinterpret_cast<const float4*>(g_partials);
    const int tid = threadIdx.x;

    float4 u = __ldg(&p[tid]);
    float4 v = __ldg(&p[tid + 1024]);
    float s = ((u.x + u.y) + (u.z + u.w)) + ((v.x + v.y) + (v.z + v.w));

    #pragma unroll
    for (int off = 16; off > 0; off >>= 1)
        s += __shfl_xor_sync(0xFFFFFFFFu, s, off);

    __shared__ float sh[32];
    if ((tid & 31) == 0)
        sh[tid >> 5] = s;
    __syncthreads();

    if (tid < 32) {
        float t = sh[tid];
        #pragma unroll
        for (int off = 16; off > 0; off >>= 1)
            t += __shfl_xor_sync(0xFFFFFFFFu, t, off);
        if (tid == 0)
            out[0] = -t * inv_batch;
    }
}

extern "C" void kernel_launch(void* const* d_in, const int* in_sizes, int n_in,
                              void* d_out, int out_size)
{
    const float* second_emb  = (const float*)d_in[0];
    const float* context_emb = (const float*)d_in[1];
    const int*   v_i         = (const int*)d_in[2];
    const int*   v_j         = (const int*)d_in[3];
    const int*   negs        = (const int*)d_in[4];

    const int batch  = in_sizes[2];                            // 131072
    const int blocks = (batch + WPB * EPW - 1) / (WPB * EPW);  // 8192

    w2v_main<<<blocks, TPB>>>(second_emb, context_emb, v_i, v_j, negs, batch);
    w2v_reduce<<<1, 1024>>>((float*)d_out, 1.0f / (float)batch);
}